// round 7
// baseline (speedup 1.0000x reference)
#include <cuda_runtime.h>
#include <cuda_fp16.h>
#include <mma.h>

using namespace nvcuda;

#define DIMD 512
#define NBATCH 4096
#define NSLOTS 64
#define M_TOTAL (NBATCH * NSLOTS)   /* 262144 rows */
#define NCLS 4
#define KTOP 16
#define NBLK 4                      /* 512 / 128 n-blocks */

#define BM 128
#define BN 128
#define BK 32
#define KSTEPS (DIMD / BK)          /* 16 */
#define STAGE_BYTES 40960           /* (A hi+lo + B hi+lo) * 128*40 halves */
#define SMEM_TOTAL (2 * STAGE_BYTES + 3072)

// ---------------- scratch (static device memory; no allocations) ----------------
__device__ __half g_w1h[DIMD * DIMD], g_w1l[DIMD * DIMD];
__device__ __half g_w2h[DIMD * DIMD], g_w2l[DIMD * DIMD];
__device__ __half g_wkh[DIMD * DIMD], g_wkl[DIMD * DIMD];
__device__ __half g_x_hi[(size_t)M_TOTAL * DIMD], g_x_lo[(size_t)M_TOTAL * DIMD]; // slots split
__device__ __half g_h_hi[(size_t)M_TOTAL * DIMD], g_h_lo[(size_t)M_TOTAL * DIMD];
__device__ __half g_s_hi[(size_t)M_TOTAL * DIMD], g_s_lo[(size_t)M_TOTAL * DIMD];
__device__ float  g_logits_part[(size_t)NBLK * M_TOTAL * NCLS];
__device__ float  g_keep_part[(size_t)NBLK * M_TOTAL];

// ---------------- weight split: fp32 -> (hi, lo) fp16 pair ----------------
__global__ void prep_kernel(const float* __restrict__ W1,
                            const float* __restrict__ W2,
                            const float* __restrict__ Wk1) {
    int i = blockIdx.x * blockDim.x + threadIdx.x;
    if (i >= DIMD * DIMD) return;
    float x;
    __half h;
    x = W1[i];  h = __float2half_rn(x); g_w1h[i] = h; g_w1l[i] = __float2half_rn(x - __half2float(h));
    x = W2[i];  h = __float2half_rn(x); g_w2h[i] = h; g_w2l[i] = __float2half_rn(x - __half2float(h));
    x = Wk1[i]; h = __float2half_rn(x); g_wkh[i] = h; g_wkl[i] = __float2half_rn(x - __half2float(h));
}

// ---------------- slots split: fp32 -> (hi, lo) fp16 pair (vectorized) ----------------
__global__ void split_slots_kernel(const float* __restrict__ S) {
    size_t i4 = (size_t)blockIdx.x * blockDim.x + threadIdx.x;  // one float4 per thread
    if (i4 >= (size_t)M_TOTAL * DIMD / 4) return;
    float4 f = *(const float4*)(S + i4 * 4);
    __half h0 = __float2half_rn(f.x), h1 = __float2half_rn(f.y);
    __half h2 = __float2half_rn(f.z), h3 = __float2half_rn(f.w);
    __half l0 = __float2half_rn(f.x - __half2float(h0));
    __half l1 = __float2half_rn(f.y - __half2float(h1));
    __half l2 = __float2half_rn(f.z - __half2float(h2));
    __half l3 = __float2half_rn(f.w - __half2float(h3));
    __half2 hp[2] = {__halves2half2(h0, h1), __halves2half2(h2, h3)};
    __half2 lp[2] = {__halves2half2(l0, l1), __halves2half2(l2, l3)};
    *(uint2*)(g_x_hi + i4 * 4) = *(uint2*)hp;
    *(uint2*)(g_x_lo + i4 * 4) = *(uint2*)lp;
}

__device__ __forceinline__ void cpa16(void* s, const void* g) {
    unsigned sa = (unsigned)__cvta_generic_to_shared(s);
    asm volatile("cp.async.cg.shared.global [%0], [%1], 16;\n" :: "r"(sa), "l"(g));
}
__device__ __forceinline__ void cpa_commit() { asm volatile("cp.async.commit_group;\n"); }
template <int N>
__device__ __forceinline__ void cpa_wait() { asm volatile("cp.async.wait_group %0;\n" :: "n"(N)); }

// ---------------- fused GEMM: C[m,n] = sum_k A[m,k] * W[n,k] (+bias, epilogue per MODE)
// MODE 1: A = slots(hi/lo), W = W1 -> relu -> g_h (hi/lo)
// MODE 2: A = g_h, W = W2 -> g_s (hi/lo) + fused slot_logits partials (s . Wd^T)
// MODE 3: A = g_s, W = Wk1 -> fused keep_score partials (relu(.) . Wk2)
// Split fp16 accuracy: acc += Ah*Bh + Ah*Bl + Al*Bh
template <int MODE>
__global__ __launch_bounds__(256, 1)
void gemm_kernel(const float* __restrict__ bias,
                 const float* __restrict__ Wd,
                 const float* __restrict__ Wk2) {
    extern __shared__ __align__(16) unsigned char dsm[];
    float* Cs     = (float*)dsm;                       // [128][132] overlay (epilogue)
    float* bias_s = (float*)(dsm + 2 * STAGE_BYTES);
    float* wd_s   = (float*)(dsm + 2 * STAGE_BYTES + 512);   // [4][128]
    float* wk_s   = (float*)(dsm + 2 * STAGE_BYTES + 2560);  // [128]

    const __half *Ahi, *Alo, *Bhi, *Blo;
    __half *Ohi = nullptr, *Olo = nullptr;
    if (MODE == 1) { Ahi = g_x_hi; Alo = g_x_lo; Bhi = g_w1h; Blo = g_w1l; Ohi = g_h_hi; Olo = g_h_lo; }
    if (MODE == 2) { Ahi = g_h_hi; Alo = g_h_lo; Bhi = g_w2h; Blo = g_w2l; Ohi = g_s_hi; Olo = g_s_lo; }
    if (MODE == 3) { Ahi = g_s_hi; Alo = g_s_lo; Bhi = g_wkh; Blo = g_wkl; }

    const int tid = threadIdx.x;
    const int n0 = blockIdx.x * BN;
    const int m0 = blockIdx.y * BM;

    if (tid < 128) bias_s[tid] = bias[n0 + tid];
    if (MODE == 2) {
#pragma unroll
        for (int idx = tid; idx < 512; idx += 256) {
            int c = idx >> 7, j = idx & 127;
            wd_s[c * 128 + j] = Wd[c * DIMD + n0 + j];
        }
    }
    if (MODE == 3 && tid < 128) wk_s[tid] = Wk2[n0 + tid];

    const int warp = tid >> 5;
    const int wm = warp & 3;    // 4 row-warps of 32 rows
    const int wn = warp >> 2;   // 2 col-warps of 64 cols

    wmma::fragment<wmma::accumulator, 16, 16, 16, float> acc[2][4];
#pragma unroll
    for (int i = 0; i < 2; i++)
#pragma unroll
        for (int j = 0; j < 4; j++) wmma::fill_fragment(acc[i][j], 0.0f);

    // staged loads: 512 16B-chunks per array per stage -> 2 per thread per array
    auto load_stage = [&](int buf, int kpos) {
        __half* Ah = (__half*)(dsm + buf * STAGE_BYTES);
        __half* Al = Ah + 128 * 40;
        __half* Bh = Al + 128 * 40;
        __half* Bl = Bh + 128 * 40;
#pragma unroll
        for (int c = tid; c < 512; c += 256) {
            int row = c >> 2, off = (c & 3) * 8;
            size_t ga = (size_t)(m0 + row) * DIMD + kpos + off;
            size_t gb = (size_t)(n0 + row) * DIMD + kpos + off;
            int so = row * 40 + off;
            cpa16(Ah + so, Ahi + ga);
            cpa16(Al + so, Alo + ga);
            cpa16(Bh + so, Bhi + gb);
            cpa16(Bl + so, Blo + gb);
        }
        cpa_commit();
    };

    load_stage(0, 0);

    for (int kt = 0; kt < KSTEPS; kt++) {
        if (kt + 1 < KSTEPS) {
            load_stage((kt + 1) & 1, (kt + 1) * BK);
            cpa_wait<1>();
        } else {
            cpa_wait<0>();
        }
        __syncthreads();

        const __half* Ah = (const __half*)(dsm + (kt & 1) * STAGE_BYTES);
        const __half* Al = Ah + 128 * 40;
        const __half* Bh = Al + 128 * 40;
        const __half* Bl = Bh + 128 * 40;

#pragma unroll
        for (int ks = 0; ks < BK; ks += 16) {
            wmma::fragment<wmma::matrix_a, 16, 16, 16, __half, wmma::row_major> ah[2], al[2];
#pragma unroll
            for (int i = 0; i < 2; i++) {
                wmma::load_matrix_sync(ah[i], Ah + (wm * 32 + i * 16) * 40 + ks, 40);
                wmma::load_matrix_sync(al[i], Al + (wm * 32 + i * 16) * 40 + ks, 40);
            }
            wmma::fragment<wmma::matrix_b, 16, 16, 16, __half, wmma::col_major> bh[4], bl[4];
#pragma unroll
            for (int j = 0; j < 4; j++) {
                wmma::load_matrix_sync(bh[j], Bh + (wn * 64 + j * 16) * 40 + ks, 40);
                wmma::load_matrix_sync(bl[j], Bl + (wn * 64 + j * 16) * 40 + ks, 40);
            }
            // three independent passes: no back-to-back same-accumulator MMAs
#pragma unroll
            for (int j = 0; j < 4; j++)
#pragma unroll
                for (int i = 0; i < 2; i++) wmma::mma_sync(acc[i][j], ah[i], bh[j], acc[i][j]);
#pragma unroll
            for (int j = 0; j < 4; j++)
#pragma unroll
                for (int i = 0; i < 2; i++) wmma::mma_sync(acc[i][j], ah[i], bl[j], acc[i][j]);
#pragma unroll
            for (int j = 0; j < 4; j++)
#pragma unroll
                for (int i = 0; i < 2; i++) wmma::mma_sync(acc[i][j], al[i], bh[j], acc[i][j]);
        }
        __syncthreads();   // protect stage buffer against next iteration's cp.async
    }

    // ---- epilogue: stash accumulators to smem ----
#pragma unroll
    for (int i = 0; i < 2; i++)
#pragma unroll
        for (int j = 0; j < 4; j++)
            wmma::store_matrix_sync(Cs + (wm * 32 + i * 16) * 132 + (wn * 64 + j * 16),
                                    acc[i][j], 132, wmma::mem_row_major);
    __syncthreads();

    const int r = tid >> 1;
    const int ch = (tid & 1) * 64;
    const size_t row_g = (size_t)m0 + r;
    float lg0 = 0.f, lg1 = 0.f, lg2 = 0.f, lg3 = 0.f, kp = 0.f;
#pragma unroll
    for (int c = 0; c < 64; c += 2) {
        int col = ch + c;
        float v0 = Cs[r * 132 + col]     + bias_s[col];
        float v1 = Cs[r * 132 + col + 1] + bias_s[col + 1];
        if (MODE == 1) { v0 = fmaxf(v0, 0.f); v1 = fmaxf(v1, 0.f); }
        if (MODE <= 2) {
            __half h0 = __float2half_rn(v0), h1 = __float2half_rn(v1);
            __half l0 = __float2half_rn(v0 - __half2float(h0));
            __half l1 = __float2half_rn(v1 - __half2float(h1));
            *(__half2*)(Ohi + row_g * DIMD + n0 + col) = __halves2half2(h0, h1);
            *(__half2*)(Olo + row_g * DIMD + n0 + col) = __halves2half2(l0, l1);
        }
        if (MODE == 2) {
            lg0 += v0 * wd_s[0 * 128 + col] + v1 * wd_s[0 * 128 + col + 1];
            lg1 += v0 * wd_s[1 * 128 + col] + v1 * wd_s[1 * 128 + col + 1];
            lg2 += v0 * wd_s[2 * 128 + col] + v1 * wd_s[2 * 128 + col + 1];
            lg3 += v0 * wd_s[3 * 128 + col] + v1 * wd_s[3 * 128 + col + 1];
        }
        if (MODE == 3) {
            kp += fmaxf(v0, 0.f) * wk_s[col] + fmaxf(v1, 0.f) * wk_s[col + 1];
        }
    }
    if (MODE == 2) {
        lg0 += __shfl_xor_sync(0xffffffffu, lg0, 1);
        lg1 += __shfl_xor_sync(0xffffffffu, lg1, 1);
        lg2 += __shfl_xor_sync(0xffffffffu, lg2, 1);
        lg3 += __shfl_xor_sync(0xffffffffu, lg3, 1);
        if ((tid & 1) == 0) {
            float4 o = make_float4(lg0, lg1, lg2, lg3);
            *(float4*)(g_logits_part + ((size_t)blockIdx.x * M_TOTAL + row_g) * 4) = o;
        }
    }
    if (MODE == 3) {
        kp += __shfl_xor_sync(0xffffffffu, kp, 1);
        if ((tid & 1) == 0)
            g_keep_part[(size_t)blockIdx.x * M_TOTAL + row_g] = kp;
    }
}

// ---------------- per-batch top-k / softmax / gating / output ----------------
__global__ void final_kernel(const float* __restrict__ bd,
                             const float* __restrict__ bk2,
                             float* __restrict__ out) {
    __shared__ float sc[NSLOTS];
    __shared__ float ex[NSLOTS];
    __shared__ float gt[NSLOTS];
    __shared__ float red[NSLOTS * NCLS];
    const int b = blockIdx.x;
    const int s = threadIdx.x;           // 64 threads, one per slot
    const size_t m = (size_t)b * NSLOTS + s;

    float score = bk2[0];
#pragma unroll
    for (int nb = 0; nb < NBLK; nb++) score += g_keep_part[(size_t)nb * M_TOTAL + m];
    sc[s] = score;
    __syncthreads();

    float mx = -1e30f; int cnt = 0;
#pragma unroll 8
    for (int j = 0; j < NSLOTS; j++) {
        float v = sc[j];
        mx = fmaxf(mx, v);
        cnt += (v > score) || (v == score && j < s);
    }
    float e = expf((score - mx) * 100.0f);  // temperature 0.01
    ex[s] = e;
    __syncthreads();
    float sum = 0.f;
#pragma unroll 8
    for (int j = 0; j < NSLOTS; j++) sum += ex[j];
    float soft = e / sum;
    float hardf = (cnt < KTOP) ? 1.0f : 0.0f;
    float hard_keep = (hardf + soft) - soft;   // matches JAX ST-estimator fp order
    float gate = soft * hard_keep;
    gt[s] = gate;
    __syncthreads();
    float gsum = 0.f;
#pragma unroll 8
    for (int j = 0; j < NSLOTS; j++) gsum += gt[j];
    gate = gate / (gsum + 1e-8f);

    out[(size_t)NBATCH * NCLS + m] = gate;                                 // slot_gate
    out[(size_t)NBATCH * NCLS + (size_t)NBATCH * NSLOTS + m] = hard_keep;  // hard_keep

#pragma unroll
    for (int c = 0; c < NCLS; c++) {
        float v = bd[c];
#pragma unroll
        for (int nb = 0; nb < NBLK; nb++)
            v += g_logits_part[((size_t)nb * M_TOTAL + m) * 4 + c];
        red[s * NCLS + c] = gate * v;
    }
    __syncthreads();
    if (s < NCLS) {
        float acc = 0.f;
#pragma unroll 8
        for (int j = 0; j < NSLOTS; j++) acc += red[j * NCLS + s];
        out[(size_t)b * NCLS + s] = acc;   // x
    }
}

extern "C" void kernel_launch(void* const* d_in, const int* in_sizes, int n_in,
                              void* d_out, int out_size) {
    const float* slots = (const float*)d_in[0];
    const float* W1    = (const float*)d_in[1];
    const float* b1    = (const float*)d_in[2];
    const float* W2    = (const float*)d_in[3];
    const float* b2    = (const float*)d_in[4];
    const float* Wd    = (const float*)d_in[5];
    const float* bd    = (const float*)d_in[6];
    const float* Wk1   = (const float*)d_in[7];
    const float* bk1   = (const float*)d_in[8];
    const float* Wk2   = (const float*)d_in[9];
    const float* bk2   = (const float*)d_in[10];
    float* out = (float*)d_out;

    cudaFuncSetAttribute(gemm_kernel<1>, cudaFuncAttributeMaxDynamicSharedMemorySize, SMEM_TOTAL);
    cudaFuncSetAttribute(gemm_kernel<2>, cudaFuncAttributeMaxDynamicSharedMemorySize, SMEM_TOTAL);
    cudaFuncSetAttribute(gemm_kernel<3>, cudaFuncAttributeMaxDynamicSharedMemorySize, SMEM_TOTAL);

    prep_kernel<<<(DIMD * DIMD + 255) / 256, 256>>>(W1, W2, Wk1);
    split_slots_kernel<<<(M_TOTAL * (DIMD / 4) + 255) / 256, 256>>>(slots);
    dim3 grid(NBLK, M_TOTAL / BM);
    gemm_kernel<1><<<grid, 256, SMEM_TOTAL>>>(b1, nullptr, nullptr);
    gemm_kernel<2><<<grid, 256, SMEM_TOTAL>>>(b2, Wd, nullptr);
    gemm_kernel<3><<<grid, 256, SMEM_TOTAL>>>(bk1, nullptr, Wk2);
    final_kernel<<<NBATCH, NSLOTS>>>(bd, bk2, out);
}

// round 10
// speedup vs baseline: 1.1210x; 1.1210x over previous
#include <cuda_runtime.h>
#include <cuda_fp16.h>
#include <mma.h>

using namespace nvcuda;

#define DIMD 512
#define NBATCH 4096
#define NSLOTS 64
#define M_TOTAL (NBATCH * NSLOTS)   /* 262144 rows */
#define NCLS 4
#define KTOP 16
#define NBLK 4                      /* 512 / 128 n-blocks */

#define BM 128
#define BN 128
#define BK 32
#define KSTEPS (DIMD / BK)          /* 16 */
#define STAGE_BYTES 40960           /* (A hi+lo + B hi+lo) * 128*40 halves */
#define SMEM_TOTAL (2 * STAGE_BYTES + 3072)

// ---------------- scratch (static device memory; no allocations) ----------------
__device__ __half g_w1h[DIMD * DIMD], g_w1l[DIMD * DIMD];
__device__ __half g_w2h[DIMD * DIMD], g_w2l[DIMD * DIMD];
__device__ __half g_wkh[DIMD * DIMD], g_wkl[DIMD * DIMD];
__device__ __half g_x_hi[(size_t)M_TOTAL * DIMD], g_x_lo[(size_t)M_TOTAL * DIMD]; // slots split
__device__ __half g_h_hi[(size_t)M_TOTAL * DIMD], g_h_lo[(size_t)M_TOTAL * DIMD];
__device__ __half g_s_hi[(size_t)M_TOTAL * DIMD], g_s_lo[(size_t)M_TOTAL * DIMD];
__device__ float  g_logits_part[(size_t)NBLK * M_TOTAL * NCLS];
__device__ float  g_keep_part[(size_t)NBLK * M_TOTAL];

// ---------------- weight split: fp32 -> (hi, lo) fp16 pair ----------------
__global__ void prep_kernel(const float* __restrict__ W1,
                            const float* __restrict__ W2,
                            const float* __restrict__ Wk1) {
    int i = blockIdx.x * blockDim.x + threadIdx.x;
    if (i >= DIMD * DIMD) return;
    float x;
    __half h;
    x = W1[i];  h = __float2half_rn(x); g_w1h[i] = h; g_w1l[i] = __float2half_rn(x - __half2float(h));
    x = W2[i];  h = __float2half_rn(x); g_w2h[i] = h; g_w2l[i] = __float2half_rn(x - __half2float(h));
    x = Wk1[i]; h = __float2half_rn(x); g_wkh[i] = h; g_wkl[i] = __float2half_rn(x - __half2float(h));
}

// ---------------- slots split: fp32 -> (hi, lo) fp16 pair (vectorized) ----------------
__global__ void split_slots_kernel(const float* __restrict__ S) {
    size_t i4 = (size_t)blockIdx.x * blockDim.x + threadIdx.x;  // one float4 per thread
    if (i4 >= (size_t)M_TOTAL * DIMD / 4) return;
    float4 f = *(const float4*)(S + i4 * 4);
    __half h0 = __float2half_rn(f.x), h1 = __float2half_rn(f.y);
    __half h2 = __float2half_rn(f.z), h3 = __float2half_rn(f.w);
    __half l0 = __float2half_rn(f.x - __half2float(h0));
    __half l1 = __float2half_rn(f.y - __half2float(h1));
    __half l2 = __float2half_rn(f.z - __half2float(h2));
    __half l3 = __float2half_rn(f.w - __half2float(h3));
    __half2 hp[2] = {__halves2half2(h0, h1), __halves2half2(h2, h3)};
    __half2 lp[2] = {__halves2half2(l0, l1), __halves2half2(l2, l3)};
    *(uint2*)(g_x_hi + i4 * 4) = *(uint2*)hp;
    *(uint2*)(g_x_lo + i4 * 4) = *(uint2*)lp;
}

__device__ __forceinline__ void cpa16(void* s, const void* g) {
    unsigned sa = (unsigned)__cvta_generic_to_shared(s);
    asm volatile("cp.async.cg.shared.global [%0], [%1], 16;\n" :: "r"(sa), "l"(g));
}
__device__ __forceinline__ void cpa_commit() { asm volatile("cp.async.commit_group;\n"); }
template <int N>
__device__ __forceinline__ void cpa_wait() { asm volatile("cp.async.wait_group %0;\n" :: "n"(N)); }

// ---------------- fused GEMM: C[m,n] = sum_k A[m,k] * W[n,k] (+bias, epilogue per MODE)
// MODE 1: A = slots(hi/lo), W = W1 -> relu -> g_h (hi/lo)
// MODE 2: A = g_h, W = W2 -> g_s (hi/lo) + fused slot_logits partials (s . Wd^T)
// MODE 3: A = g_s, W = Wk1 -> fused keep_score partials (relu(.) . Wk2)
// Split fp16 accuracy: acc += Ah*Bh + Ah*Bl + Al*Bh
template <int MODE>
__global__ __launch_bounds__(256, 2)
void gemm_kernel(const float* __restrict__ bias,
                 const float* __restrict__ Wd,
                 const float* __restrict__ Wk2) {
    extern __shared__ __align__(16) unsigned char dsm[];
    float* Cs     = (float*)dsm;                       // [128][132] overlay (epilogue)
    float* bias_s = (float*)(dsm + 2 * STAGE_BYTES);
    float* wd_s   = (float*)(dsm + 2 * STAGE_BYTES + 512);   // [4][128]
    float* wk_s   = (float*)(dsm + 2 * STAGE_BYTES + 2560);  // [128]

    const __half *Ahi, *Alo, *Bhi, *Blo;
    __half *Ohi = nullptr, *Olo = nullptr;
    if (MODE == 1) { Ahi = g_x_hi; Alo = g_x_lo; Bhi = g_w1h; Blo = g_w1l; Ohi = g_h_hi; Olo = g_h_lo; }
    if (MODE == 2) { Ahi = g_h_hi; Alo = g_h_lo; Bhi = g_w2h; Blo = g_w2l; Ohi = g_s_hi; Olo = g_s_lo; }
    if (MODE == 3) { Ahi = g_s_hi; Alo = g_s_lo; Bhi = g_wkh; Blo = g_wkl; }

    const int tid = threadIdx.x;
    const int n0 = blockIdx.x * BN;
    const int m0 = blockIdx.y * BM;

    if (tid < 128) bias_s[tid] = bias[n0 + tid];
    if (MODE == 2) {
#pragma unroll
        for (int idx = tid; idx < 512; idx += 256) {
            int c = idx >> 7, j = idx & 127;
            wd_s[c * 128 + j] = Wd[c * DIMD + n0 + j];
        }
    }
    if (MODE == 3 && tid < 128) wk_s[tid] = Wk2[n0 + tid];

    const int warp = tid >> 5;
    const int wm = warp & 3;    // 4 row-warps of 32 rows
    const int wn = warp >> 2;   // 2 col-warps of 64 cols

    wmma::fragment<wmma::accumulator, 16, 16, 16, float> acc[2][4];
#pragma unroll
    for (int i = 0; i < 2; i++)
#pragma unroll
        for (int j = 0; j < 4; j++) wmma::fill_fragment(acc[i][j], 0.0f);

    // staged loads: 512 16B-chunks per array per stage -> 2 per thread per array
    auto load_stage = [&](int buf, int kpos) {
        __half* Ah = (__half*)(dsm + buf * STAGE_BYTES);
        __half* Al = Ah + 128 * 40;
        __half* Bh = Al + 128 * 40;
        __half* Bl = Bh + 128 * 40;
#pragma unroll
        for (int c = tid; c < 512; c += 256) {
            int row = c >> 2, off = (c & 3) * 8;
            size_t ga = (size_t)(m0 + row) * DIMD + kpos + off;
            size_t gb = (size_t)(n0 + row) * DIMD + kpos + off;
            int so = row * 40 + off;
            cpa16(Ah + so, Ahi + ga);
            cpa16(Al + so, Alo + ga);
            cpa16(Bh + so, Bhi + gb);
            cpa16(Bl + so, Blo + gb);
        }
        cpa_commit();
    };

    load_stage(0, 0);

    for (int kt = 0; kt < KSTEPS; kt++) {
        if (kt + 1 < KSTEPS) {
            load_stage((kt + 1) & 1, (kt + 1) * BK);
            cpa_wait<1>();
        } else {
            cpa_wait<0>();
        }
        __syncthreads();

        const __half* Ah = (const __half*)(dsm + (kt & 1) * STAGE_BYTES);
        const __half* Al = Ah + 128 * 40;
        const __half* Bh = Al + 128 * 40;
        const __half* Bl = Bh + 128 * 40;

#pragma unroll
        for (int ks = 0; ks < BK; ks += 16) {
            wmma::fragment<wmma::matrix_a, 16, 16, 16, __half, wmma::row_major> ah[2], al[2];
#pragma unroll
            for (int i = 0; i < 2; i++) {
                wmma::load_matrix_sync(ah[i], Ah + (wm * 32 + i * 16) * 40 + ks, 40);
                wmma::load_matrix_sync(al[i], Al + (wm * 32 + i * 16) * 40 + ks, 40);
            }
            // one B fragment live at a time: keeps regs <= 128 for 2 CTAs/SM
#pragma unroll
            for (int j = 0; j < 4; j++) {
                wmma::fragment<wmma::matrix_b, 16, 16, 16, __half, wmma::col_major> b;
                wmma::load_matrix_sync(b, Bh + (wn * 64 + j * 16) * 40 + ks, 40);
                wmma::mma_sync(acc[0][j], ah[0], b, acc[0][j]);
                wmma::mma_sync(acc[1][j], ah[1], b, acc[1][j]);
                wmma::mma_sync(acc[0][j], al[0], b, acc[0][j]);
                wmma::mma_sync(acc[1][j], al[1], b, acc[1][j]);
                wmma::load_matrix_sync(b, Bl + (wn * 64 + j * 16) * 40 + ks, 40);
                wmma::mma_sync(acc[0][j], ah[0], b, acc[0][j]);
                wmma::mma_sync(acc[1][j], ah[1], b, acc[1][j]);
            }
        }
        __syncthreads();   // protect stage buffer against next iteration's cp.async
    }

    // ---- epilogue: stash accumulators to smem ----
#pragma unroll
    for (int i = 0; i < 2; i++)
#pragma unroll
        for (int j = 0; j < 4; j++)
            wmma::store_matrix_sync(Cs + (wm * 32 + i * 16) * 132 + (wn * 64 + j * 16),
                                    acc[i][j], 132, wmma::mem_row_major);
    __syncthreads();

    const int r = tid >> 1;
    const int ch = (tid & 1) * 64;
    const size_t row_g = (size_t)m0 + r;
    float lg0 = 0.f, lg1 = 0.f, lg2 = 0.f, lg3 = 0.f, kp = 0.f;
#pragma unroll
    for (int c = 0; c < 64; c += 2) {
        int col = ch + c;
        float v0 = Cs[r * 132 + col]     + bias_s[col];
        float v1 = Cs[r * 132 + col + 1] + bias_s[col + 1];
        if (MODE == 1) { v0 = fmaxf(v0, 0.f); v1 = fmaxf(v1, 0.f); }
        if (MODE <= 2) {
            __half h0 = __float2half_rn(v0), h1 = __float2half_rn(v1);
            __half l0 = __float2half_rn(v0 - __half2float(h0));
            __half l1 = __float2half_rn(v1 - __half2float(h1));
            *(__half2*)(Ohi + row_g * DIMD + n0 + col) = __halves2half2(h0, h1);
            *(__half2*)(Olo + row_g * DIMD + n0 + col) = __halves2half2(l0, l1);
        }
        if (MODE == 2) {
            lg0 += v0 * wd_s[0 * 128 + col] + v1 * wd_s[0 * 128 + col + 1];
            lg1 += v0 * wd_s[1 * 128 + col] + v1 * wd_s[1 * 128 + col + 1];
            lg2 += v0 * wd_s[2 * 128 + col] + v1 * wd_s[2 * 128 + col + 1];
            lg3 += v0 * wd_s[3 * 128 + col] + v1 * wd_s[3 * 128 + col + 1];
        }
        if (MODE == 3) {
            kp += fmaxf(v0, 0.f) * wk_s[col] + fmaxf(v1, 0.f) * wk_s[col + 1];
        }
    }
    if (MODE == 2) {
        lg0 += __shfl_xor_sync(0xffffffffu, lg0, 1);
        lg1 += __shfl_xor_sync(0xffffffffu, lg1, 1);
        lg2 += __shfl_xor_sync(0xffffffffu, lg2, 1);
        lg3 += __shfl_xor_sync(0xffffffffu, lg3, 1);
        if ((tid & 1) == 0) {
            float4 o = make_float4(lg0, lg1, lg2, lg3);
            *(float4*)(g_logits_part + ((size_t)blockIdx.x * M_TOTAL + row_g) * 4) = o;
        }
    }
    if (MODE == 3) {
        kp += __shfl_xor_sync(0xffffffffu, kp, 1);
        if ((tid & 1) == 0)
            g_keep_part[(size_t)blockIdx.x * M_TOTAL + row_g] = kp;
    }
}

// ---------------- per-batch top-k / softmax / gating / output ----------------
__global__ void final_kernel(const float* __restrict__ bd,
                             const float* __restrict__ bk2,
                             float* __restrict__ out) {
    __shared__ float sc[NSLOTS];
    __shared__ float ex[NSLOTS];
    __shared__ float gt[NSLOTS];
    __shared__ float red[NSLOTS * NCLS];
    const int b = blockIdx.x;
    const int s = threadIdx.x;           // 64 threads, one per slot
    const size_t m = (size_t)b * NSLOTS + s;

    float score = bk2[0];
#pragma unroll
    for (int nb = 0; nb < NBLK; nb++) score += g_keep_part[(size_t)nb * M_TOTAL + m];
    sc[s] = score;
    __syncthreads();

    float mx = -1e30f; int cnt = 0;
#pragma unroll 8
    for (int j = 0; j < NSLOTS; j++) {
        float v = sc[j];
        mx = fmaxf(mx, v);
        cnt += (v > score) || (v == score && j < s);
    }
    float e = expf((score - mx) * 100.0f);  // temperature 0.01
    ex[s] = e;
    __syncthreads();
    float sum = 0.f;
#pragma unroll 8
    for (int j = 0; j < NSLOTS; j++) sum += ex[j];
    float soft = e / sum;
    float hardf = (cnt < KTOP) ? 1.0f : 0.0f;
    float hard_keep = (hardf + soft) - soft;   // matches JAX ST-estimator fp order
    float gate = soft * hard_keep;
    gt[s] = gate;
    __syncthreads();
    float gsum = 0.f;
#pragma unroll 8
    for (int j = 0; j < NSLOTS; j++) gsum += gt[j];
    gate = gate / (gsum + 1e-8f);

    out[(size_t)NBATCH * NCLS + m] = gate;                                 // slot_gate
    out[(size_t)NBATCH * NCLS + (size_t)NBATCH * NSLOTS + m] = hard_keep;  // hard_keep

#pragma unroll
    for (int c = 0; c < NCLS; c++) {
        float v = bd[c];
#pragma unroll
        for (int nb = 0; nb < NBLK; nb++)
            v += g_logits_part[((size_t)nb * M_TOTAL + m) * 4 + c];
        red[s * NCLS + c] = gate * v;
    }
    __syncthreads();
    if (s < NCLS) {
        float acc = 0.f;
#pragma unroll 8
        for (int j = 0; j < NSLOTS; j++) acc += red[j * NCLS + s];
        out[(size_t)b * NCLS + s] = acc;   // x
    }
}

extern "C" void kernel_launch(void* const* d_in, const int* in_sizes, int n_in,
                              void* d_out, int out_size) {
    const float* slots = (const float*)d_in[0];
    const float* W1    = (const float*)d_in[1];
    const float* b1    = (const float*)d_in[2];
    const float* W2    = (const float*)d_in[3];
    const float* b2    = (const float*)d_in[4];
    const float* Wd    = (const float*)d_in[5];
    const float* bd    = (const float*)d_in[6];
    const float* Wk1   = (const float*)d_in[7];
    const float* bk1   = (const float*)d_in[8];
    const float* Wk2   = (const float*)d_in[9];
    const float* bk2   = (const float*)d_in[10];
    float* out = (float*)d_out;

    cudaFuncSetAttribute(gemm_kernel<1>, cudaFuncAttributeMaxDynamicSharedMemorySize, SMEM_TOTAL);
    cudaFuncSetAttribute(gemm_kernel<2>, cudaFuncAttributeMaxDynamicSharedMemorySize, SMEM_TOTAL);
    cudaFuncSetAttribute(gemm_kernel<3>, cudaFuncAttributeMaxDynamicSharedMemorySize, SMEM_TOTAL);

    prep_kernel<<<(DIMD * DIMD + 255) / 256, 256>>>(W1, W2, Wk1);
    split_slots_kernel<<<(M_TOTAL * (DIMD / 4) + 255) / 256, 256>>>(slots);
    dim3 grid(NBLK, M_TOTAL / BM);
    gemm_kernel<1><<<grid, 256, SMEM_TOTAL>>>(b1, nullptr, nullptr);
    gemm_kernel<2><<<grid, 256, SMEM_TOTAL>>>(b2, Wd, nullptr);
    gemm_kernel<3><<<grid, 256, SMEM_TOTAL>>>(bk1, nullptr, Wk2);
    final_kernel<<<NBATCH, NSLOTS>>>(bd, bk2, out);
}

// round 14
// speedup vs baseline: 1.1334x; 1.0110x over previous
#include <cuda_runtime.h>
#include <cuda_fp16.h>
#include <mma.h>

using namespace nvcuda;

#define DIMD 512
#define NBATCH 4096
#define NSLOTS 64
#define M_TOTAL (NBATCH * NSLOTS)   /* 262144 rows */
#define NCLS 4
#define KTOP 16
#define NBLK 4                      /* 512 / 128 n-blocks */

#define BM 128
#define BN 128
#define BK 32
#define KSTEPS (DIMD / BK)          /* 16 */
#define STAGE_BYTES 40960           /* (A hi+lo + B hi+lo) * 128*40 halves */
#define SMEM_TOTAL (2 * STAGE_BYTES + 3072)

// ---------------- scratch (static device memory; no allocations) ----------------
__device__ __half g_w1h[DIMD * DIMD], g_w1l[DIMD * DIMD];
__device__ __half g_w2h[DIMD * DIMD], g_w2l[DIMD * DIMD];
__device__ __half g_wkh[DIMD * DIMD], g_wkl[DIMD * DIMD];
__device__ __half g_x_hi[(size_t)M_TOTAL * DIMD], g_x_lo[(size_t)M_TOTAL * DIMD]; // slots split
__device__ __half g_h_hi[(size_t)M_TOTAL * DIMD], g_h_lo[(size_t)M_TOTAL * DIMD];
__device__ __half g_s_hi[(size_t)M_TOTAL * DIMD], g_s_lo[(size_t)M_TOTAL * DIMD];
__device__ float  g_logits_part[(size_t)NBLK * M_TOTAL * NCLS];
__device__ float  g_keep_part[(size_t)NBLK * M_TOTAL];

// ---------------- weight split: fp32 -> (hi, lo) fp16 pair ----------------
__global__ void prep_kernel(const float* __restrict__ W1,
                            const float* __restrict__ W2,
                            const float* __restrict__ Wk1) {
    int i = blockIdx.x * blockDim.x + threadIdx.x;
    if (i >= DIMD * DIMD) return;
    float x;
    __half h;
    x = W1[i];  h = __float2half_rn(x); g_w1h[i] = h; g_w1l[i] = __float2half_rn(x - __half2float(h));
    x = W2[i];  h = __float2half_rn(x); g_w2h[i] = h; g_w2l[i] = __float2half_rn(x - __half2float(h));
    x = Wk1[i]; h = __float2half_rn(x); g_wkh[i] = h; g_wkl[i] = __float2half_rn(x - __half2float(h));
}

// ---------------- slots split: fp32 -> (hi, lo) fp16 pair (vectorized) ----------------
__global__ void split_slots_kernel(const float* __restrict__ S) {
    size_t i4 = (size_t)blockIdx.x * blockDim.x + threadIdx.x;  // one float4 per thread
    if (i4 >= (size_t)M_TOTAL * DIMD / 4) return;
    float4 f = *(const float4*)(S + i4 * 4);
    __half h0 = __float2half_rn(f.x), h1 = __float2half_rn(f.y);
    __half h2 = __float2half_rn(f.z), h3 = __float2half_rn(f.w);
    __half l0 = __float2half_rn(f.x - __half2float(h0));
    __half l1 = __float2half_rn(f.y - __half2float(h1));
    __half l2 = __float2half_rn(f.z - __half2float(h2));
    __half l3 = __float2half_rn(f.w - __half2float(h3));
    __half2 hp[2] = {__halves2half2(h0, h1), __halves2half2(h2, h3)};
    __half2 lp[2] = {__halves2half2(l0, l1), __halves2half2(l2, l3)};
    *(uint2*)(g_x_hi + i4 * 4) = *(uint2*)hp;
    *(uint2*)(g_x_lo + i4 * 4) = *(uint2*)lp;
}

__device__ __forceinline__ void cpa16(void* s, const void* g) {
    unsigned sa = (unsigned)__cvta_generic_to_shared(s);
    asm volatile("cp.async.cg.shared.global [%0], [%1], 16;\n" :: "r"(sa), "l"(g));
}
__device__ __forceinline__ void cpa_commit() { asm volatile("cp.async.commit_group;\n"); }
template <int N>
__device__ __forceinline__ void cpa_wait() { asm volatile("cp.async.wait_group %0;\n" :: "n"(N)); }

// ---------------- fused GEMM: C[m,n] = sum_k A[m,k] * W[n,k] (+bias, epilogue per MODE)
// MODE 1: A = slots(hi/lo), W = W1 -> relu -> g_h (hi/lo)
// MODE 2: A = g_h, W = W2 -> g_s (hi/lo) + fused slot_logits partials (s . Wd^T)
// MODE 3: A = g_s, W = Wk1 -> fused keep_score partials (relu(.) . Wk2)
// Split fp16 accuracy: acc += Ah*Bh + Ah*Bl + Al*Bh
template <int MODE>
__global__ __launch_bounds__(256, 2)
void gemm_kernel(const float* __restrict__ bias,
                 const float* __restrict__ Wd,
                 const float* __restrict__ Wk2) {
    extern __shared__ __align__(16) unsigned char dsm[];
    float* Cs     = (float*)dsm;                       // [128][132] overlay (epilogue)
    float* bias_s = (float*)(dsm + 2 * STAGE_BYTES);
    float* wd_s   = (float*)(dsm + 2 * STAGE_BYTES + 512);   // [4][128]
    float* wk_s   = (float*)(dsm + 2 * STAGE_BYTES + 2560);  // [128]

    const __half *Ahi, *Alo, *Bhi, *Blo;
    __half *Ohi = nullptr, *Olo = nullptr;
    if (MODE == 1) { Ahi = g_x_hi; Alo = g_x_lo; Bhi = g_w1h; Blo = g_w1l; Ohi = g_h_hi; Olo = g_h_lo; }
    if (MODE == 2) { Ahi = g_h_hi; Alo = g_h_lo; Bhi = g_w2h; Blo = g_w2l; Ohi = g_s_hi; Olo = g_s_lo; }
    if (MODE == 3) { Ahi = g_s_hi; Alo = g_s_lo; Bhi = g_wkh; Blo = g_wkl; }

    const int tid = threadIdx.x;
    const int n0 = blockIdx.x * BN;
    const int m0 = blockIdx.y * BM;

    if (tid < 128) bias_s[tid] = bias[n0 + tid];
    if (MODE == 2) {
#pragma unroll
        for (int idx = tid; idx < 512; idx += 256) {
            int c = idx >> 7, j = idx & 127;
            wd_s[c * 128 + j] = Wd[c * DIMD + n0 + j];
        }
    }
    if (MODE == 3 && tid < 128) wk_s[tid] = Wk2[n0 + tid];

    const int warp = tid >> 5;
    const int wm = warp & 3;    // 4 row-warps of 32 rows
    const int wn = warp >> 2;   // 2 col-warps of 64 cols

    wmma::fragment<wmma::accumulator, 16, 16, 16, float> acc[2][4];
#pragma unroll
    for (int i = 0; i < 2; i++)
#pragma unroll
        for (int j = 0; j < 4; j++) wmma::fill_fragment(acc[i][j], 0.0f);

    // staged loads: 512 16B-chunks per array per stage -> 2 per thread per array
    auto load_stage = [&](int buf, int kpos) {
        __half* Ah = (__half*)(dsm + buf * STAGE_BYTES);
        __half* Al = Ah + 128 * 40;
        __half* Bh = Al + 128 * 40;
        __half* Bl = Bh + 128 * 40;
#pragma unroll
        for (int c = tid; c < 512; c += 256) {
            int row = c >> 2, off = (c & 3) * 8;
            size_t ga = (size_t)(m0 + row) * DIMD + kpos + off;
            size_t gb = (size_t)(n0 + row) * DIMD + kpos + off;
            int so = row * 40 + off;
            cpa16(Ah + so, Ahi + ga);
            cpa16(Al + so, Alo + ga);
            cpa16(Bh + so, Bhi + gb);
            cpa16(Bl + so, Blo + gb);
        }
        cpa_commit();
    };

    load_stage(0, 0);

    for (int kt = 0; kt < KSTEPS; kt++) {
        // single-sync pipeline: wait stage kt -> sync (also proves stage kt-1 fully
        // consumed by all warps) -> refill kt-1's buffer with stage kt+1 -> compute kt
        cpa_wait<0>();
        __syncthreads();
        if (kt + 1 < KSTEPS) load_stage((kt + 1) & 1, (kt + 1) * BK);

        const __half* Ah = (const __half*)(dsm + (kt & 1) * STAGE_BYTES);
        const __half* Al = Ah + 128 * 40;
        const __half* Bh = Al + 128 * 40;
        const __half* Bl = Bh + 128 * 40;

#pragma unroll
        for (int ks = 0; ks < BK; ks += 16) {
            wmma::fragment<wmma::matrix_a, 16, 16, 16, __half, wmma::row_major> ah[2], al[2];
#pragma unroll
            for (int i = 0; i < 2; i++) {
                wmma::load_matrix_sync(ah[i], Ah + (wm * 32 + i * 16) * 40 + ks, 40);
                wmma::load_matrix_sync(al[i], Al + (wm * 32 + i * 16) * 40 + ks, 40);
            }
            // pairs of B columns, pass-major: every accumulator reused at distance 4
#pragma unroll
            for (int jp = 0; jp < 2; jp++) {
                const int j0 = jp * 2, j1 = jp * 2 + 1;
                wmma::fragment<wmma::matrix_b, 16, 16, 16, __half, wmma::col_major> b0, b1;
                wmma::load_matrix_sync(b0, Bh + (wn * 64 + j0 * 16) * 40 + ks, 40);
                wmma::load_matrix_sync(b1, Bh + (wn * 64 + j1 * 16) * 40 + ks, 40);
                wmma::mma_sync(acc[0][j0], ah[0], b0, acc[0][j0]);
                wmma::mma_sync(acc[1][j0], ah[1], b0, acc[1][j0]);
                wmma::mma_sync(acc[0][j1], ah[0], b1, acc[0][j1]);
                wmma::mma_sync(acc[1][j1], ah[1], b1, acc[1][j1]);
                wmma::mma_sync(acc[0][j0], al[0], b0, acc[0][j0]);
                wmma::mma_sync(acc[1][j0], al[1], b0, acc[1][j0]);
                wmma::mma_sync(acc[0][j1], al[0], b1, acc[0][j1]);
                wmma::mma_sync(acc[1][j1], al[1], b1, acc[1][j1]);
                wmma::load_matrix_sync(b0, Bl + (wn * 64 + j0 * 16) * 40 + ks, 40);
                wmma::load_matrix_sync(b1, Bl + (wn * 64 + j1 * 16) * 40 + ks, 40);
                wmma::mma_sync(acc[0][j0], ah[0], b0, acc[0][j0]);
                wmma::mma_sync(acc[1][j0], ah[1], b0, acc[1][j0]);
                wmma::mma_sync(acc[0][j1], ah[0], b1, acc[0][j1]);
                wmma::mma_sync(acc[1][j1], ah[1], b1, acc[1][j1]);
            }
        }
    }
    __syncthreads();   // all warps done with final stage before Cs overlays staging smem

    // ---- epilogue: stash accumulators to smem ----
#pragma unroll
    for (int i = 0; i < 2; i++)
#pragma unroll
        for (int j = 0; j < 4; j++)
            wmma::store_matrix_sync(Cs + (wm * 32 + i * 16) * 132 + (wn * 64 + j * 16),
                                    acc[i][j], 132, wmma::mem_row_major);
    __syncthreads();

    const int r = tid >> 1;
    const int ch = (tid & 1) * 64;
    const size_t row_g = (size_t)m0 + r;
    float lg0 = 0.f, lg1 = 0.f, lg2 = 0.f, lg3 = 0.f, kp = 0.f;
#pragma unroll
    for (int c = 0; c < 64; c += 2) {
        int col = ch + c;
        float v0 = Cs[r * 132 + col]     + bias_s[col];
        float v1 = Cs[r * 132 + col + 1] + bias_s[col + 1];
        if (MODE == 1) { v0 = fmaxf(v0, 0.f); v1 = fmaxf(v1, 0.f); }
        if (MODE <= 2) {
            __half h0 = __float2half_rn(v0), h1 = __float2half_rn(v1);
            __half l0 = __float2half_rn(v0 - __half2float(h0));
            __half l1 = __float2half_rn(v1 - __half2float(h1));
            *(__half2*)(Ohi + row_g * DIMD + n0 + col) = __halves2half2(h0, h1);
            *(__half2*)(Olo + row_g * DIMD + n0 + col) = __halves2half2(l0, l1);
        }
        if (MODE == 2) {
            lg0 += v0 * wd_s[0 * 128 + col] + v1 * wd_s[0 * 128 + col + 1];
            lg1 += v0 * wd_s[1 * 128 + col] + v1 * wd_s[1 * 128 + col + 1];
            lg2 += v0 * wd_s[2 * 128 + col] + v1 * wd_s[2 * 128 + col + 1];
            lg3 += v0 * wd_s[3 * 128 + col] + v1 * wd_s[3 * 128 + col + 1];
        }
        if (MODE == 3) {
            kp += fmaxf(v0, 0.f) * wk_s[col] + fmaxf(v1, 0.f) * wk_s[col + 1];
        }
    }
    if (MODE == 2) {
        lg0 += __shfl_xor_sync(0xffffffffu, lg0, 1);
        lg1 += __shfl_xor_sync(0xffffffffu, lg1, 1);
        lg2 += __shfl_xor_sync(0xffffffffu, lg2, 1);
        lg3 += __shfl_xor_sync(0xffffffffu, lg3, 1);
        if ((tid & 1) == 0) {
            float4 o = make_float4(lg0, lg1, lg2, lg3);
            *(float4*)(g_logits_part + ((size_t)blockIdx.x * M_TOTAL + row_g) * 4) = o;
        }
    }
    if (MODE == 3) {
        kp += __shfl_xor_sync(0xffffffffu, kp, 1);
        if ((tid & 1) == 0)
            g_keep_part[(size_t)blockIdx.x * M_TOTAL + row_g] = kp;
    }
}

// ---------------- per-batch top-k / softmax / gating / output ----------------
__global__ void final_kernel(const float* __restrict__ bd,
                             const float* __restrict__ bk2,
                             float* __restrict__ out) {
    __shared__ float sc[NSLOTS];
    __shared__ float ex[NSLOTS];
    __shared__ float gt[NSLOTS];
    __shared__ float red[NSLOTS * NCLS];
    const int b = blockIdx.x;
    const int s = threadIdx.x;           // 64 threads, one per slot
    const size_t m = (size_t)b * NSLOTS + s;

    float score = bk2[0];
#pragma unroll
    for (int nb = 0; nb < NBLK; nb++) score += g_keep_part[(size_t)nb * M_TOTAL + m];
    sc[s] = score;
    __syncthreads();

    float mx = -1e30f; int cnt = 0;
#pragma unroll 8
    for (int j = 0; j < NSLOTS; j++) {
        float v = sc[j];
        mx = fmaxf(mx, v);
        cnt += (v > score) || (v == score && j < s);
    }
    float e = expf((score - mx) * 100.0f);  // temperature 0.01
    ex[s] = e;
    __syncthreads();
    float sum = 0.f;
#pragma unroll 8
    for (int j = 0; j < NSLOTS; j++) sum += ex[j];
    float soft = e / sum;
    float hardf = (cnt < KTOP) ? 1.0f : 0.0f;
    float hard_keep = (hardf + soft) - soft;   // matches JAX ST-estimator fp order
    float gate = soft * hard_keep;
    gt[s] = gate;
    __syncthreads();
    float gsum = 0.f;
#pragma unroll 8
    for (int j = 0; j < NSLOTS; j++) gsum += gt[j];
    gate = gate / (gsum + 1e-8f);

    out[(size_t)NBATCH * NCLS + m] = gate;                                 // slot_gate
    out[(size_t)NBATCH * NCLS + (size_t)NBATCH * NSLOTS + m] = hard_keep;  // hard_keep

#pragma unroll
    for (int c = 0; c < NCLS; c++) {
        float v = bd[c];
#pragma unroll
        for (int nb = 0; nb < NBLK; nb++)
            v += g_logits_part[((size_t)nb * M_TOTAL + m) * 4 + c];
        red[s * NCLS + c] = gate * v;
    }
    __syncthreads();
    if (s < NCLS) {
        float acc = 0.f;
#pragma unroll 8
        for (int j = 0; j < NSLOTS; j++) acc += red[j * NCLS + s];
        out[(size_t)b * NCLS + s] = acc;   // x
    }
}

extern "C" void kernel_launch(void* const* d_in, const int* in_sizes, int n_in,
                              void* d_out, int out_size) {
    const float* slots = (const float*)d_in[0];
    const float* W1    = (const float*)d_in[1];
    const float* b1    = (const float*)d_in[2];
    const float* W2    = (const float*)d_in[3];
    const float* b2    = (const float*)d_in[4];
    const float* Wd    = (const float*)d_in[5];
    const float* bd    = (const float*)d_in[6];
    const float* Wk1   = (const float*)d_in[7];
    const float* bk1   = (const float*)d_in[8];
    const float* Wk2   = (const float*)d_in[9];
    const float* bk2   = (const float*)d_in[10];
    float* out = (float*)d_out;

    cudaFuncSetAttribute(gemm_kernel<1>, cudaFuncAttributeMaxDynamicSharedMemorySize, SMEM_TOTAL);
    cudaFuncSetAttribute(gemm_kernel<2>, cudaFuncAttributeMaxDynamicSharedMemorySize, SMEM_TOTAL);
    cudaFuncSetAttribute(gemm_kernel<3>, cudaFuncAttributeMaxDynamicSharedMemorySize, SMEM_TOTAL);

    prep_kernel<<<(DIMD * DIMD + 255) / 256, 256>>>(W1, W2, Wk1);
    split_slots_kernel<<<(M_TOTAL * (DIMD / 4) + 255) / 256, 256>>>(slots);
    dim3 grid(NBLK, M_TOTAL / BM);
    gemm_kernel<1><<<grid, 256, SMEM_TOTAL>>>(b1, nullptr, nullptr);
    gemm_kernel<2><<<grid, 256, SMEM_TOTAL>>>(b2, Wd, nullptr);
    gemm_kernel<3><<<grid, 256, SMEM_TOTAL>>>(bk1, nullptr, Wk2);
    final_kernel<<<NBATCH, NSLOTS>>>(bd, bk2, out);
}